// round 7
// baseline (speedup 1.0000x reference)
#include <cuda_runtime.h>
#include <cstdint>

#define BATCH 4
#define CKD   64
#define CVD   512
#define NMEM  9216
#define MQ    2304
#define NT    128
#define NTILES (NMEM / NT)   // 72
#define STR   132            // padded smem row stride (floats)

// smem layout (float offsets)
#define OQ   0
#define OKS  (OQ  + CKD * STR)    //  8448
#define OP   (OKS + CKD * STR)    // 16896  P[m 128][n 128]
#define OV   (OP  + NT  * STR)    // 33792  V[cv 128][n 128]
#define ORA  (OV  + NT  * STR)    // 50688
#define ORB  (ORA + 128)
#define OINV (ORB + 128)
#define SM_FLOATS (OINV + 128)
#define SMEM_BYTES (SM_FLOATS * 4)   // 204,288 B

// ---------------------------------------------------------------------------
__device__ __forceinline__ uint32_t s2u(const void* p) {
    uint32_t a;
    asm("{.reg .u64 t; cvta.to.shared.u64 t, %1; cvt.u32.u64 %0, t;}" : "=r"(a) : "l"(p));
    return a;
}
__device__ __forceinline__ void cpa16(uint32_t s, const void* g) {
    asm volatile("cp.async.cg.shared.global [%0], [%1], 16;" :: "r"(s), "l"(g));
}
#define CP_COMMIT() asm volatile("cp.async.commit_group;" ::: "memory")
#define CP_WAIT(N)  asm volatile("cp.async.wait_group %0;" :: "n"(N) : "memory")

// Round fp32 -> tf32 (rna), result in fp32 bit layout (low 13 bits zero).
__device__ __forceinline__ uint32_t tf32r(float x) {
    uint32_t r;
    asm("cvt.rna.tf32.f32 %0, %1;" : "=r"(r) : "f"(x));
    return r;
}
__device__ __forceinline__ void split2(float x, uint32_t& hi, uint32_t& lo) {
    hi = tf32r(x);
    lo = tf32r(x - __uint_as_float(hi));
}

// m16n8k8 tf32 mma (fp32 accumulate).
__device__ __forceinline__ void mma8(float c[4], const uint32_t a[4],
                                     uint32_t b0, uint32_t b1) {
    asm volatile(
        "mma.sync.aligned.m16n8k8.row.col.f32.tf32.tf32.f32 "
        "{%0,%1,%2,%3}, {%4,%5,%6,%7}, {%8,%9}, {%0,%1,%2,%3};"
        : "+f"(c[0]), "+f"(c[1]), "+f"(c[2]), "+f"(c[3])
        : "r"(a[0]), "r"(a[1]), "r"(a[2]), "r"(a[3]), "r"(b0), "r"(b1));
}

// ---------------------------------------------------------------------------
__global__ __launch_bounds__(256, 1)
void mr_kernel(const float* __restrict__ mk, const float* __restrict__ qk,
               const float* __restrict__ mv, float* __restrict__ out) {
    extern __shared__ float sm[];
    const int t = threadIdx.x, wid = t >> 5, lane = t & 31;
    const int g = lane >> 2, tig = lane & 3;
    const int wm = wid & 3, wn = wid >> 2;
    const int b = blockIdx.z;
    const int m0 = blockIdx.x * 128, cv0 = blockIdx.y * 128;

    const float* qb = qk + (size_t)b * CKD * MQ + m0;
    const float* kb = mk + (size_t)b * CKD * NMEM;
    const float* vb = mv + ((size_t)b * CVD + cv0) * NMEM;

    // ---- prologue: Q + K0 (group A), V0 (group B) ----
#pragma unroll
    for (int i = 0; i < 8; i++) {
        int idx = t + 256 * i, c = idx >> 5, q = (idx & 31) * 4;
        cpa16(s2u(sm + OQ + c * STR + q), qb + (size_t)c * MQ + q);
    }
#pragma unroll
    for (int i = 0; i < 8; i++) {
        int idx = t + 256 * i, c = idx >> 5, q = (idx & 31) * 4;
        cpa16(s2u(sm + OKS + c * STR + q), kb + (size_t)c * NMEM + q);
    }
    CP_COMMIT();
#pragma unroll
    for (int i = 0; i < 16; i++) {
        int idx = t + 256 * i, cv = idx >> 5, q = (idx & 31) * 4;
        cpa16(s2u(sm + OV + cv * STR + q), vb + (size_t)cv * NMEM + q);
    }
    CP_COMMIT();

    float oacc[2][8][4] = {};
    float rsum[4] = {0.f, 0.f, 0.f, 0.f};

    for (int tt = 0; tt < NTILES; tt++) {
        CP_WAIT(1);               // Q/K_tt done (V_tt may still be in flight)
        __syncthreads();

        // ---- GEMM1: S[m][n] = Q·K^T, 3-term split tf32 (K=64) ----
        float sacc[2][8][4] = {};
        {
            const int mb = wm * 32, nb = wn * 64;
#pragma unroll 2
            for (int j = 0; j < 8; j++) {
                const int k0 = 8 * j + tig;
                uint32_t ah[2][4], al[2][4];
#pragma unroll
                for (int i = 0; i < 2; i++) {
                    split2(sm[OQ + k0 * STR + mb + 16 * i + g],           ah[i][0], al[i][0]);
                    split2(sm[OQ + k0 * STR + mb + 16 * i + g + 8],       ah[i][1], al[i][1]);
                    split2(sm[OQ + (k0 + 4) * STR + mb + 16 * i + g],     ah[i][2], al[i][2]);
                    split2(sm[OQ + (k0 + 4) * STR + mb + 16 * i + g + 8], ah[i][3], al[i][3]);
                }
#pragma unroll 4
                for (int f = 0; f < 8; f++) {
                    uint32_t b0h, b0l, b1h, b1l;
                    split2(sm[OKS + k0 * STR + nb + 8 * f + g],       b0h, b0l);
                    split2(sm[OKS + (k0 + 4) * STR + nb + 8 * f + g], b1h, b1l);
                    mma8(sacc[0][f], ah[0], b0h, b1h);
                    mma8(sacc[1][f], ah[1], b0h, b1h);
                    mma8(sacc[0][f], al[0], b0h, b1h);
                    mma8(sacc[1][f], al[1], b0h, b1h);
                    mma8(sacc[0][f], ah[0], b0l, b1l);
                    mma8(sacc[1][f], ah[1], b0l, b1l);
                }
            }
        }
        __syncthreads();          // Ks free -> prefetch K_{tt+1}
        if (tt + 1 < NTILES) {
            const float* kb2 = kb + (size_t)(tt + 1) * NT;
#pragma unroll
            for (int i = 0; i < 8; i++) {
                int idx = t + 256 * i, c = idx >> 5, q = (idx & 31) * 4;
                cpa16(s2u(sm + OKS + c * STR + q), kb2 + (size_t)c * NMEM + q);
            }
            CP_COMMIT();
        }

        // ---- epilogue: exp -> P (pre-rounded to exact tf32), row sums ----
        {
            const int mb = wm * 32, nb = wn * 64;
            float ps[4] = {0.f, 0.f, 0.f, 0.f};
#pragma unroll
            for (int i = 0; i < 2; i++)
#pragma unroll 4
                for (int f = 0; f < 8; f++) {
                    float e0 = __uint_as_float(tf32r(__expf(sacc[i][f][0] * 0.125f)));
                    float e1 = __uint_as_float(tf32r(__expf(sacc[i][f][1] * 0.125f)));
                    float e2 = __uint_as_float(tf32r(__expf(sacc[i][f][2] * 0.125f)));
                    float e3 = __uint_as_float(tf32r(__expf(sacc[i][f][3] * 0.125f)));
                    ps[2 * i]     += e0 + e1;
                    ps[2 * i + 1] += e2 + e3;
                    int col = nb + 8 * f + 2 * tig;
                    *(float2*)&sm[OP + (mb + 16 * i + g) * STR + col] =
                        make_float2(e0, e1);
                    *(float2*)&sm[OP + (mb + 16 * i + g + 8) * STR + col] =
                        make_float2(e2, e3);
                }
#pragma unroll
            for (int q = 0; q < 4; q++) {
                ps[q] += __shfl_xor_sync(0xffffffffu, ps[q], 1);
                ps[q] += __shfl_xor_sync(0xffffffffu, ps[q], 2);
                rsum[q] += ps[q];
            }
        }
        if (tt + 1 < NTILES) { CP_WAIT(1); } else { CP_WAIT(0); }   // V_tt done
        __syncthreads();          // Ps visible + V ready

        // ---- GEMM2: O^T[cv][m] += V·P^T, 2-term split on V (K=128) ----
        {
            const int cb = wm * 32, mb2 = wn * 64;
#pragma unroll 2
            for (int u = 0; u < 16; u++) {
                const int k0 = 8 * u + tig;
                uint32_t ah[2][4], al[2][4];
#pragma unroll
                for (int i = 0; i < 2; i++) {
                    split2(sm[OV + (cb + 16 * i + g) * STR + k0],         ah[i][0], al[i][0]);
                    split2(sm[OV + (cb + 16 * i + g + 8) * STR + k0],     ah[i][1], al[i][1]);
                    split2(sm[OV + (cb + 16 * i + g) * STR + k0 + 4],     ah[i][2], al[i][2]);
                    split2(sm[OV + (cb + 16 * i + g + 8) * STR + k0 + 4], ah[i][3], al[i][3]);
                }
#pragma unroll 4
                for (int f = 0; f < 8; f++) {
                    uint32_t b0 = __float_as_uint(sm[OP + (mb2 + 8 * f + g) * STR + k0]);
                    uint32_t b1 = __float_as_uint(sm[OP + (mb2 + 8 * f + g) * STR + k0 + 4]);
                    mma8(oacc[0][f], ah[0], b0, b1);
                    mma8(oacc[1][f], ah[1], b0, b1);
                    mma8(oacc[0][f], al[0], b0, b1);
                    mma8(oacc[1][f], al[1], b0, b1);
                }
            }
        }
        __syncthreads();          // Vs/Ps free -> prefetch V_{tt+1}
        if (tt + 1 < NTILES) {
            const float* vb2 = vb + (size_t)(tt + 1) * NT;
#pragma unroll
            for (int i = 0; i < 16; i++) {
                int idx = t + 256 * i, cv = idx >> 5, q = (idx & 31) * 4;
                cpa16(s2u(sm + OV + cv * STR + q), vb2 + (size_t)cv * NMEM + q);
            }
            CP_COMMIT();
        }
    }

    // ---- finalize: row sums -> inv, normalize + store O^T ----
    if (tig == 0) {
        float* rs = (wn == 0) ? (sm + ORA) : (sm + ORB);
        const int mb = wm * 32;
        rs[mb + g]      = rsum[0];
        rs[mb + g + 8]  = rsum[1];
        rs[mb + g + 16] = rsum[2];
        rs[mb + g + 24] = rsum[3];
    }
    __syncthreads();
    if (t < 128) sm[OINV + t] = 1.0f / (sm[ORA + t] + sm[ORB + t]);
    __syncthreads();

    {
        const int cb = wm * 32, mb2 = wn * 64;
#pragma unroll
        for (int i = 0; i < 2; i++)
#pragma unroll 4
            for (int f = 0; f < 8; f++) {
                int m_ = mb2 + 8 * f + 2 * tig;
                float iv0 = sm[OINV + m_], iv1 = sm[OINV + m_ + 1];
                int cv = cb + 16 * i + g;
                float* o0 = out + ((size_t)b * CVD + cv0 + cv) * MQ + m0 + m_;
                float* o1 = o0 + (size_t)8 * MQ;
                *(float2*)o0 = make_float2(oacc[i][f][0] * iv0, oacc[i][f][1] * iv1);
                *(float2*)o1 = make_float2(oacc[i][f][2] * iv0, oacc[i][f][3] * iv1);
            }
    }
}

// ---------------------------------------------------------------------------
extern "C" void kernel_launch(void* const* d_in, const int* in_sizes, int n_in,
                              void* d_out, int out_size) {
    const float* mk = (const float*)d_in[0];
    const float* qk = (const float*)d_in[1];
    const float* mv = (const float*)d_in[2];
    float* out = (float*)d_out;

    cudaFuncSetAttribute(mr_kernel, cudaFuncAttributeMaxDynamicSharedMemorySize,
                         SMEM_BYTES);
    dim3 grid(MQ / 128, CVD / 128, BATCH);   // 18 x 4 x 4 = 288
    mr_kernel<<<grid, 256, SMEM_BYTES>>>(mk, qk, mv, out);
}

// round 8
// speedup vs baseline: 3.5606x; 3.5606x over previous
#include <cuda_runtime.h>
#include <cstdint>

#define BATCH 4
#define CKD   64
#define CVD   512
#define NMEM  9216
#define MQ    2304
#define NT    128
#define NTILES (NMEM / NT)   // 72
#define STR   132            // padded smem row stride (floats)
#define THREADS 512

// smem layout (float offsets)
#define OQ   0
#define OKS  (OQ  + CKD * STR)    //  8448
#define OP   (OKS + CKD * STR)    // 16896  P[m 128][n 128]
#define OV   (OP  + NT  * STR)    // 33792  V[cv 128][n 128]
#define ORA  (OV  + NT  * STR)    // 50688  row-sum partials [4 wn][128 m]
#define OINV (ORA + 512)
#define SM_FLOATS (OINV + 128)
#define SMEM_BYTES (SM_FLOATS * 4)   // 205,312 B

// ---------------------------------------------------------------------------
__device__ __forceinline__ uint32_t s2u(const void* p) {
    uint32_t a;
    asm("{.reg .u64 t; cvta.to.shared.u64 t, %1; cvt.u32.u64 %0, t;}" : "=r"(a) : "l"(p));
    return a;
}
__device__ __forceinline__ void cpa16(uint32_t s, const void* g) {
    asm volatile("cp.async.cg.shared.global [%0], [%1], 16;" :: "r"(s), "l"(g));
}
#define CP_COMMIT() asm volatile("cp.async.commit_group;" ::: "memory")
#define CP_WAIT(N)  asm volatile("cp.async.wait_group %0;" :: "n"(N) : "memory")

// Round fp32 -> tf32 (rna) — used only in the epilogue for P.
__device__ __forceinline__ uint32_t tf32r(float x) {
    uint32_t r;
    asm("cvt.rna.tf32.f32 %0, %1;" : "=r"(r) : "f"(x));
    return r;
}
// Cheap exact split: hi = trunc-to-tf32 (mask), lo = x - hi (exact fp32).
// hi + lo == x exactly; mma's HW truncation of lo loses only ~2^-21 * x.
__device__ __forceinline__ void fsplit(float x, uint32_t& hi, uint32_t& lo) {
    hi = __float_as_uint(x) & 0xFFFFE000u;
    lo = __float_as_uint(x - __uint_as_float(hi));
}

// m16n8k8 tf32 mma (fp32 accumulate).
__device__ __forceinline__ void mma8(float c[4], const uint32_t a[4],
                                     uint32_t b0, uint32_t b1) {
    asm volatile(
        "mma.sync.aligned.m16n8k8.row.col.f32.tf32.tf32.f32 "
        "{%0,%1,%2,%3}, {%4,%5,%6,%7}, {%8,%9}, {%0,%1,%2,%3};"
        : "+f"(c[0]), "+f"(c[1]), "+f"(c[2]), "+f"(c[3])
        : "r"(a[0]), "r"(a[1]), "r"(a[2]), "r"(a[3]), "r"(b0), "r"(b1));
}

// ---------------------------------------------------------------------------
__global__ __launch_bounds__(THREADS, 1)
void mr_kernel(const float* __restrict__ mk, const float* __restrict__ qk,
               const float* __restrict__ mv, float* __restrict__ out) {
    extern __shared__ float sm[];
    const int t = threadIdx.x, wid = t >> 5, lane = t & 31;
    const int g = lane >> 2, tig = lane & 3;
    const int wm = wid & 3, wn = wid >> 2;          // 4 x 4 warp grid
    const int b = blockIdx.z;
    const int m0 = blockIdx.x * 128, cv0 = blockIdx.y * 128;

    const float* qb = qk + (size_t)b * CKD * MQ + m0;
    const float* kb = mk + (size_t)b * CKD * NMEM;
    const float* vb = mv + ((size_t)b * CVD + cv0) * NMEM;

    // ---- prologue: Q + K0 (group A), V0 (group B) ----
#pragma unroll
    for (int i = 0; i < 4; i++) {
        int idx = t + THREADS * i, c = idx >> 5, q = (idx & 31) * 4;
        cpa16(s2u(sm + OQ + c * STR + q), qb + (size_t)c * MQ + q);
    }
#pragma unroll
    for (int i = 0; i < 4; i++) {
        int idx = t + THREADS * i, c = idx >> 5, q = (idx & 31) * 4;
        cpa16(s2u(sm + OKS + c * STR + q), kb + (size_t)c * NMEM + q);
    }
    CP_COMMIT();
#pragma unroll
    for (int i = 0; i < 8; i++) {
        int idx = t + THREADS * i, cv = idx >> 5, q = (idx & 31) * 4;
        cpa16(s2u(sm + OV + cv * STR + q), vb + (size_t)cv * NMEM + q);
    }
    CP_COMMIT();

    float oacc[2][4][4] = {};
    float rsum[4] = {0.f, 0.f, 0.f, 0.f};

    for (int tt = 0; tt < NTILES; tt++) {
        CP_WAIT(1);               // Q/K_tt done (V_tt may still be in flight)
        __syncthreads();

        // ---- GEMM1: S[m][n] = Q·K^T, 3-term split tf32 (K=64) ----
        float sacc[2][4][4] = {};
        {
            const int mb = wm * 32, nb = wn * 32;
#pragma unroll 2
            for (int j = 0; j < 8; j++) {
                const int k0 = 8 * j + tig;
                uint32_t ah[2][4], al[2][4];
#pragma unroll
                for (int i = 0; i < 2; i++) {
                    fsplit(sm[OQ + k0 * STR + mb + 16 * i + g],           ah[i][0], al[i][0]);
                    fsplit(sm[OQ + k0 * STR + mb + 16 * i + g + 8],       ah[i][1], al[i][1]);
                    fsplit(sm[OQ + (k0 + 4) * STR + mb + 16 * i + g],     ah[i][2], al[i][2]);
                    fsplit(sm[OQ + (k0 + 4) * STR + mb + 16 * i + g + 8], ah[i][3], al[i][3]);
                }
#pragma unroll
                for (int f = 0; f < 4; f++) {
                    uint32_t b0h, b0l, b1h, b1l;
                    fsplit(sm[OKS + k0 * STR + nb + 8 * f + g],       b0h, b0l);
                    fsplit(sm[OKS + (k0 + 4) * STR + nb + 8 * f + g], b1h, b1l);
                    mma8(sacc[0][f], ah[0], b0h, b1h);
                    mma8(sacc[1][f], ah[1], b0h, b1h);
                    mma8(sacc[0][f], al[0], b0h, b1h);
                    mma8(sacc[1][f], al[1], b0h, b1h);
                    mma8(sacc[0][f], ah[0], b0l, b1l);
                    mma8(sacc[1][f], ah[1], b0l, b1l);
                }
            }
        }
        __syncthreads();          // Ks free -> prefetch K_{tt+1}
        if (tt + 1 < NTILES) {
            const float* kb2 = kb + (size_t)(tt + 1) * NT;
#pragma unroll
            for (int i = 0; i < 4; i++) {
                int idx = t + THREADS * i, c = idx >> 5, q = (idx & 31) * 4;
                cpa16(s2u(sm + OKS + c * STR + q), kb2 + (size_t)c * NMEM + q);
            }
            CP_COMMIT();
        }

        // ---- epilogue: exp -> P (pre-rounded to exact tf32), row sums ----
        {
            const int mb = wm * 32, nb = wn * 32;
            float ps[4] = {0.f, 0.f, 0.f, 0.f};
#pragma unroll
            for (int i = 0; i < 2; i++)
#pragma unroll
                for (int f = 0; f < 4; f++) {
                    float e0 = __uint_as_float(tf32r(__expf(sacc[i][f][0] * 0.125f)));
                    float e1 = __uint_as_float(tf32r(__expf(sacc[i][f][1] * 0.125f)));
                    float e2 = __uint_as_float(tf32r(__expf(sacc[i][f][2] * 0.125f)));
                    float e3 = __uint_as_float(tf32r(__expf(sacc[i][f][3] * 0.125f)));
                    ps[2 * i]     += e0 + e1;
                    ps[2 * i + 1] += e2 + e3;
                    int col = nb + 8 * f + 2 * tig;
                    *(float2*)&sm[OP + (mb + 16 * i + g) * STR + col] =
                        make_float2(e0, e1);
                    *(float2*)&sm[OP + (mb + 16 * i + g + 8) * STR + col] =
                        make_float2(e2, e3);
                }
#pragma unroll
            for (int q = 0; q < 4; q++) {
                ps[q] += __shfl_xor_sync(0xffffffffu, ps[q], 1);
                ps[q] += __shfl_xor_sync(0xffffffffu, ps[q], 2);
                rsum[q] += ps[q];
            }
        }
        if (tt + 1 < NTILES) { CP_WAIT(1); } else { CP_WAIT(0); }   // V_tt done
        __syncthreads();          // Ps visible + V ready

        // ---- GEMM2: O^T[cv][m] += V·P^T, 2-term split on V (K=128) ----
        {
            const int cb = wm * 32, mb2 = wn * 32;
#pragma unroll 2
            for (int u = 0; u < 16; u++) {
                const int k0 = 8 * u + tig;
                uint32_t ah[2][4], al[2][4];
#pragma unroll
                for (int i = 0; i < 2; i++) {
                    fsplit(sm[OV + (cb + 16 * i + g) * STR + k0],         ah[i][0], al[i][0]);
                    fsplit(sm[OV + (cb + 16 * i + g + 8) * STR + k0],     ah[i][1], al[i][1]);
                    fsplit(sm[OV + (cb + 16 * i + g) * STR + k0 + 4],     ah[i][2], al[i][2]);
                    fsplit(sm[OV + (cb + 16 * i + g + 8) * STR + k0 + 4], ah[i][3], al[i][3]);
                }
#pragma unroll
                for (int f = 0; f < 4; f++) {
                    uint32_t b0 = __float_as_uint(sm[OP + (mb2 + 8 * f + g) * STR + k0]);
                    uint32_t b1 = __float_as_uint(sm[OP + (mb2 + 8 * f + g) * STR + k0 + 4]);
                    mma8(oacc[0][f], ah[0], b0, b1);
                    mma8(oacc[1][f], ah[1], b0, b1);
                    mma8(oacc[0][f], al[0], b0, b1);
                    mma8(oacc[1][f], al[1], b0, b1);
                }
            }
        }
        __syncthreads();          // Vs/Ps free -> prefetch V_{tt+1}
        if (tt + 1 < NTILES) {
            const float* vb2 = vb + (size_t)(tt + 1) * NT;
#pragma unroll
            for (int i = 0; i < 8; i++) {
                int idx = t + THREADS * i, cv = idx >> 5, q = (idx & 31) * 4;
                cpa16(s2u(sm + OV + cv * STR + q), vb2 + (size_t)cv * NMEM + q);
            }
            CP_COMMIT();
        }
    }

    // ---- finalize: row sums -> inv, normalize + store O^T ----
    if (tig == 0) {
        float* rs = sm + ORA + wn * 128;
        const int mb = wm * 32;
        rs[mb + g]      = rsum[0];
        rs[mb + g + 8]  = rsum[1];
        rs[mb + g + 16] = rsum[2];
        rs[mb + g + 24] = rsum[3];
    }
    __syncthreads();
    if (t < 128)
        sm[OINV + t] = 1.0f / (sm[ORA + t] + sm[ORA + 128 + t] +
                               sm[ORA + 256 + t] + sm[ORA + 384 + t]);
    __syncthreads();

    {
        const int cb = wm * 32, mb2 = wn * 32;
#pragma unroll
        for (int i = 0; i < 2; i++)
#pragma unroll
            for (int f = 0; f < 4; f++) {
                int m_ = mb2 + 8 * f + 2 * tig;
                float iv0 = sm[OINV + m_], iv1 = sm[OINV + m_ + 1];
                int cv = cb + 16 * i + g;
                float* o0 = out + ((size_t)b * CVD + cv0 + cv) * MQ + m0 + m_;
                float* o1 = o0 + (size_t)8 * MQ;
                *(float2*)o0 = make_float2(oacc[i][f][0] * iv0, oacc[i][f][1] * iv1);
                *(float2*)o1 = make_float2(oacc[i][f][2] * iv0, oacc[i][f][3] * iv1);
            }
    }
}

// ---------------------------------------------------------------------------
extern "C" void kernel_launch(void* const* d_in, const int* in_sizes, int n_in,
                              void* d_out, int out_size) {
    const float* mk = (const float*)d_in[0];
    const float* qk = (const float*)d_in[1];
    const float* mv = (const float*)d_in[2];
    float* out = (float*)d_out;

    cudaFuncSetAttribute(mr_kernel, cudaFuncAttributeMaxDynamicSharedMemorySize,
                         SMEM_BYTES);
    dim3 grid(MQ / 128, CVD / 128, BATCH);   // 18 x 4 x 4 = 288
    mr_kernel<<<grid, THREADS, SMEM_BYTES>>>(mk, qk, mv, out);
}

// round 9
// speedup vs baseline: 4.9985x; 1.4038x over previous
#include <cuda_runtime.h>
#include <cstdint>

#define BATCH 4
#define CKD   64
#define CVD   512
#define NMEM  9216
#define MQ    2304
#define NT    128
#define NTILES (NMEM / NT)   // 72
#define STR   132            // padded smem row stride (floats)
#define THREADS 512

// smem layout (float offsets)
#define OQ   0
#define OKS  (OQ  + CKD * STR)    //  8448
#define OP   (OKS + CKD * STR)    // 16896  P[m 128][n 128]
#define OV   (OP  + NT  * STR)    // 33792  V[cv 128][n 128]
#define ORA  (OV  + NT  * STR)    // 50688  row-sum partials [4 wn][128 m]
#define OINV (ORA + 512)
#define SM_FLOATS (OINV + 128)
#define SMEM_BYTES (SM_FLOATS * 4)   // 205,312 B

// ---------------------------------------------------------------------------
__device__ __forceinline__ uint32_t s2u(const void* p) {
    uint32_t a;
    asm("{.reg .u64 t; cvta.to.shared.u64 t, %1; cvt.u32.u64 %0, t;}" : "=r"(a) : "l"(p));
    return a;
}
__device__ __forceinline__ void cpa16(uint32_t s, const void* g) {
    asm volatile("cp.async.cg.shared.global [%0], [%1], 16;" :: "r"(s), "l"(g));
}
#define CP_COMMIT() asm volatile("cp.async.commit_group;" ::: "memory")
#define CP_WAIT(N)  asm volatile("cp.async.wait_group %0;" :: "n"(N) : "memory")

// Round fp32 -> tf32 (rna): unbiased single-operand rounding.
__device__ __forceinline__ uint32_t tf32r(float x) {
    uint32_t r;
    asm("cvt.rna.tf32.f32 %0, %1;" : "=r"(r) : "f"(x));
    return r;
}
// Cheap exact split: hi = trunc-to-tf32 (mask), lo = x - hi (exact; hi+lo==x).
__device__ __forceinline__ void fsplit(float x, uint32_t& hi, uint32_t& lo) {
    hi = __float_as_uint(x) & 0xFFFFE000u;
    lo = __float_as_uint(x - __uint_as_float(hi));
}

// m16n8k8 tf32 mma (fp32 accumulate).
__device__ __forceinline__ void mma8(float c[4], const uint32_t a[4],
                                     uint32_t b0, uint32_t b1) {
    asm volatile(
        "mma.sync.aligned.m16n8k8.row.col.f32.tf32.tf32.f32 "
        "{%0,%1,%2,%3}, {%4,%5,%6,%7}, {%8,%9}, {%0,%1,%2,%3};"
        : "+f"(c[0]), "+f"(c[1]), "+f"(c[2]), "+f"(c[3])
        : "r"(a[0]), "r"(a[1]), "r"(a[2]), "r"(a[3]), "r"(b0), "r"(b1));
}

// ---------------------------------------------------------------------------
__global__ __launch_bounds__(THREADS, 1)
void mr_kernel(const float* __restrict__ mk, const float* __restrict__ qk,
               const float* __restrict__ mv, float* __restrict__ out) {
    extern __shared__ float sm[];
    const int t = threadIdx.x, wid = t >> 5, lane = t & 31;
    const int g = lane >> 2, tig = lane & 3;
    const int wm = wid & 3, wn = wid >> 2;          // 4 x 4 warp grid
    const int b = blockIdx.z;
    const int m0 = blockIdx.x * 128, cv0 = blockIdx.y * 128;

    const float* qb = qk + (size_t)b * CKD * MQ + m0;
    const float* kb = mk + (size_t)b * CKD * NMEM;
    const float* vb = mv + ((size_t)b * CVD + cv0) * NMEM;

    // ---- prologue: Q + K0 (group A), V0 (group B) ----
#pragma unroll
    for (int i = 0; i < 4; i++) {
        int idx = t + THREADS * i, c = idx >> 5, q = (idx & 31) * 4;
        cpa16(s2u(sm + OQ + c * STR + q), qb + (size_t)c * MQ + q);
    }
#pragma unroll
    for (int i = 0; i < 4; i++) {
        int idx = t + THREADS * i, c = idx >> 5, q = (idx & 31) * 4;
        cpa16(s2u(sm + OKS + c * STR + q), kb + (size_t)c * NMEM + q);
    }
    CP_COMMIT();
#pragma unroll
    for (int i = 0; i < 8; i++) {
        int idx = t + THREADS * i, cv = idx >> 5, q = (idx & 31) * 4;
        cpa16(s2u(sm + OV + cv * STR + q), vb + (size_t)cv * NMEM + q);
    }
    CP_COMMIT();

    float oacc[2][4][4] = {};
    float rsum[4] = {0.f, 0.f, 0.f, 0.f};

    for (int tt = 0; tt < NTILES; tt++) {
        CP_WAIT(1);               // Q/K_tt done (V_tt may still be in flight)
        __syncthreads();

        // ---- GEMM1: S = (Qh+Ql)·rna(K)^T  — 2-term split tf32 (K=64) ----
        float sacc[2][4][4] = {};
        {
            const int mb = wm * 32, nb = wn * 32;
#pragma unroll 2
            for (int j = 0; j < 8; j++) {
                const int k0 = 8 * j + tig;
                uint32_t ah[2][4], al[2][4];
#pragma unroll
                for (int i = 0; i < 2; i++) {
                    fsplit(sm[OQ + k0 * STR + mb + 16 * i + g],           ah[i][0], al[i][0]);
                    fsplit(sm[OQ + k0 * STR + mb + 16 * i + g + 8],       ah[i][1], al[i][1]);
                    fsplit(sm[OQ + (k0 + 4) * STR + mb + 16 * i + g],     ah[i][2], al[i][2]);
                    fsplit(sm[OQ + (k0 + 4) * STR + mb + 16 * i + g + 8], ah[i][3], al[i][3]);
                }
#pragma unroll
                for (int f = 0; f < 4; f++) {
                    uint32_t b0r = tf32r(sm[OKS + k0 * STR + nb + 8 * f + g]);
                    uint32_t b1r = tf32r(sm[OKS + (k0 + 4) * STR + nb + 8 * f + g]);
                    mma8(sacc[0][f], ah[0], b0r, b1r);
                    mma8(sacc[1][f], ah[1], b0r, b1r);
                    mma8(sacc[0][f], al[0], b0r, b1r);
                    mma8(sacc[1][f], al[1], b0r, b1r);
                }
            }
        }
        __syncthreads();          // Ks free -> prefetch K_{tt+1}
        if (tt + 1 < NTILES) {
            const float* kb2 = kb + (size_t)(tt + 1) * NT;
#pragma unroll
            for (int i = 0; i < 4; i++) {
                int idx = t + THREADS * i, c = idx >> 5, q = (idx & 31) * 4;
                cpa16(s2u(sm + OKS + c * STR + q), kb2 + (size_t)c * NMEM + q);
            }
            CP_COMMIT();
        }

        // ---- epilogue: exp -> P (pre-rounded to exact tf32), row sums ----
        {
            const int mb = wm * 32, nb = wn * 32;
            float ps[4] = {0.f, 0.f, 0.f, 0.f};
#pragma unroll
            for (int i = 0; i < 2; i++)
#pragma unroll
                for (int f = 0; f < 4; f++) {
                    float e0 = __uint_as_float(tf32r(__expf(sacc[i][f][0] * 0.125f)));
                    float e1 = __uint_as_float(tf32r(__expf(sacc[i][f][1] * 0.125f)));
                    float e2 = __uint_as_float(tf32r(__expf(sacc[i][f][2] * 0.125f)));
                    float e3 = __uint_as_float(tf32r(__expf(sacc[i][f][3] * 0.125f)));
                    ps[2 * i]     += e0 + e1;
                    ps[2 * i + 1] += e2 + e3;
                    int col = nb + 8 * f + 2 * tig;
                    *(float2*)&sm[OP + (mb + 16 * i + g) * STR + col] =
                        make_float2(e0, e1);
                    *(float2*)&sm[OP + (mb + 16 * i + g + 8) * STR + col] =
                        make_float2(e2, e3);
                }
#pragma unroll
            for (int q = 0; q < 4; q++) {
                ps[q] += __shfl_xor_sync(0xffffffffu, ps[q], 1);
                ps[q] += __shfl_xor_sync(0xffffffffu, ps[q], 2);
                rsum[q] += ps[q];
            }
        }
        if (tt + 1 < NTILES) { CP_WAIT(1); } else { CP_WAIT(0); }   // V_tt done
        __syncthreads();          // Ps visible + V ready

        // ---- GEMM2: O^T += rna(V)·P^T — 1-term tf32 (K=128) ----
        {
            const int cb = wm * 32, mb2 = wn * 32;
#pragma unroll 2
            for (int u = 0; u < 16; u++) {
                const int k0 = 8 * u + tig;
                uint32_t ar[2][4];
#pragma unroll
                for (int i = 0; i < 2; i++) {
                    ar[i][0] = tf32r(sm[OV + (cb + 16 * i + g) * STR + k0]);
                    ar[i][1] = tf32r(sm[OV + (cb + 16 * i + g + 8) * STR + k0]);
                    ar[i][2] = tf32r(sm[OV + (cb + 16 * i + g) * STR + k0 + 4]);
                    ar[i][3] = tf32r(sm[OV + (cb + 16 * i + g + 8) * STR + k0 + 4]);
                }
#pragma unroll
                for (int f = 0; f < 4; f++) {
                    uint32_t b0 = __float_as_uint(sm[OP + (mb2 + 8 * f + g) * STR + k0]);
                    uint32_t b1 = __float_as_uint(sm[OP + (mb2 + 8 * f + g) * STR + k0 + 4]);
                    mma8(oacc[0][f], ar[0], b0, b1);
                    mma8(oacc[1][f], ar[1], b0, b1);
                }
            }
        }
        __syncthreads();          // Vs/Ps free -> prefetch V_{tt+1}
        if (tt + 1 < NTILES) {
            const float* vb2 = vb + (size_t)(tt + 1) * NT;
#pragma unroll
            for (int i = 0; i < 8; i++) {
                int idx = t + THREADS * i, cv = idx >> 5, q = (idx & 31) * 4;
                cpa16(s2u(sm + OV + cv * STR + q), vb2 + (size_t)cv * NMEM + q);
            }
            CP_COMMIT();
        }
    }

    // ---- finalize: row sums -> inv, normalize + store O^T ----
    if (tig == 0) {
        float* rs = sm + ORA + wn * 128;
        const int mb = wm * 32;
        rs[mb + g]      = rsum[0];
        rs[mb + g + 8]  = rsum[1];
        rs[mb + g + 16] = rsum[2];
        rs[mb + g + 24] = rsum[3];
    }
    __syncthreads();
    if (t < 128)
        sm[OINV + t] = 1.0f / (sm[ORA + t] + sm[ORA + 128 + t] +
                               sm[ORA + 256 + t] + sm[ORA + 384 + t]);
    __syncthreads();

    {
        const int cb = wm * 32, mb2 = wn * 32;
#pragma unroll
        for (int i = 0; i < 2; i++)
#pragma unroll
            for (int f = 0; f < 4; f++) {
                int m_ = mb2 + 8 * f + 2 * tig;
                float iv0 = sm[OINV + m_], iv1 = sm[OINV + m_ + 1];
                int cv = cb + 16 * i + g;
                float* o0 = out + ((size_t)b * CVD + cv0 + cv) * MQ + m0 + m_;
                float* o1 = o0 + (size_t)8 * MQ;
                *(float2*)o0 = make_float2(oacc[i][f][0] * iv0, oacc[i][f][1] * iv1);
                *(float2*)o1 = make_float2(oacc[i][f][2] * iv0, oacc[i][f][3] * iv1);
            }
    }
}

// ---------------------------------------------------------------------------
extern "C" void kernel_launch(void* const* d_in, const int* in_sizes, int n_in,
                              void* d_out, int out_size) {
    const float* mk = (const float*)d_in[0];
    const float* qk = (const float*)d_in[1];
    const float* mv = (const float*)d_in[2];
    float* out = (float*)d_out;

    cudaFuncSetAttribute(mr_kernel, cudaFuncAttributeMaxDynamicSharedMemorySize,
                         SMEM_BYTES);
    dim3 grid(MQ / 128, CVD / 128, BATCH);   // 18 x 4 x 4 = 288
    mr_kernel<<<grid, THREADS, SMEM_BYTES>>>(mk, qk, mv, out);
}

// round 10
// speedup vs baseline: 5.3000x; 1.0603x over previous
#include <cuda_runtime.h>
#include <cstdint>

#define BATCH 4
#define CKD   64
#define CVD   512
#define NMEM  9216
#define MQ    2304
#define NT    128
#define NTILES (NMEM / NT)   // 72
#define STR   132            // padded smem row stride (floats)
#define THREADS 512

// smem layout (float offsets)
#define OQ   0
#define OKS  (OQ  + CKD * STR)    //  8448
#define OP   (OKS + CKD * STR)    // 16896  P[m 128][n 128]
#define OV   (OP  + NT  * STR)    // 33792  V[cv 128][n 128]
#define ORA  (OV  + NT  * STR)    // 50688  row-sum partials [4 wn][128 m]
#define OINV (ORA + 512)
#define SM_FLOATS (OINV + 128)
#define SMEM_BYTES (SM_FLOATS * 4)   // 205,312 B

// ---------------------------------------------------------------------------
__device__ __forceinline__ uint32_t s2u(const void* p) {
    uint32_t a;
    asm("{.reg .u64 t; cvta.to.shared.u64 t, %1; cvt.u32.u64 %0, t;}" : "=r"(a) : "l"(p));
    return a;
}
__device__ __forceinline__ void cpa16(uint32_t s, const void* g) {
    asm volatile("cp.async.cg.shared.global [%0], [%1], 16;" :: "r"(s), "l"(g));
}
#define CP_COMMIT() asm volatile("cp.async.commit_group;" ::: "memory")
#define CP_WAIT(N)  asm volatile("cp.async.wait_group %0;" :: "n"(N) : "memory")

// Round fp32 -> tf32 (rna): unbiased single-operand rounding.
__device__ __forceinline__ uint32_t tf32r(float x) {
    uint32_t r;
    asm("cvt.rna.tf32.f32 %0, %1;" : "=r"(r) : "f"(x));
    return r;
}

// m16n8k8 tf32 mma (fp32 accumulate).
__device__ __forceinline__ void mma8(float c[4], const uint32_t a[4],
                                     uint32_t b0, uint32_t b1) {
    asm volatile(
        "mma.sync.aligned.m16n8k8.row.col.f32.tf32.tf32.f32 "
        "{%0,%1,%2,%3}, {%4,%5,%6,%7}, {%8,%9}, {%0,%1,%2,%3};"
        : "+f"(c[0]), "+f"(c[1]), "+f"(c[2]), "+f"(c[3])
        : "r"(a[0]), "r"(a[1]), "r"(a[2]), "r"(a[3]), "r"(b0), "r"(b1));
}

// ---------------------------------------------------------------------------
__global__ __launch_bounds__(THREADS, 1)
void mr_kernel(const float* __restrict__ mk, const float* __restrict__ qk,
               const float* __restrict__ mv, float* __restrict__ out) {
    extern __shared__ float sm[];
    const int t = threadIdx.x, wid = t >> 5, lane = t & 31;
    const int g = lane >> 2, tig = lane & 3;
    const int wm = wid & 3, wn = wid >> 2;          // 4 x 4 warp grid
    const int b = blockIdx.z;
    const int m0 = blockIdx.x * 128, cv0 = blockIdx.y * 128;

    const float* qb = qk + (size_t)b * CKD * MQ + m0;
    const float* kb = mk + (size_t)b * CKD * NMEM;
    const float* vb = mv + ((size_t)b * CVD + cv0) * NMEM;

    // ---- prologue: Q + K0 (group A), V0 (group B) ----
#pragma unroll
    for (int i = 0; i < 4; i++) {
        int idx = t + THREADS * i, c = idx >> 5, q = (idx & 31) * 4;
        cpa16(s2u(sm + OQ + c * STR + q), qb + (size_t)c * MQ + q);
    }
#pragma unroll
    for (int i = 0; i < 4; i++) {
        int idx = t + THREADS * i, c = idx >> 5, q = (idx & 31) * 4;
        cpa16(s2u(sm + OKS + c * STR + q), kb + (size_t)c * NMEM + q);
    }
    CP_COMMIT();
#pragma unroll
    for (int i = 0; i < 8; i++) {
        int idx = t + THREADS * i, cv = idx >> 5, q = (idx & 31) * 4;
        cpa16(s2u(sm + OV + cv * STR + q), vb + (size_t)cv * NMEM + q);
    }
    CP_COMMIT();

    // Pre-round Q to tf32 in place, once for all 72 tiles.
    CP_WAIT(1);
    __syncthreads();
#pragma unroll
    for (int i = 0; i < 16; i++) {
        int idx = t + THREADS * i;               // 8192 = 64 x 128
        int c = idx >> 7, col = idx & 127;
        sm[OQ + c * STR + col] =
            __uint_as_float(tf32r(sm[OQ + c * STR + col]));
    }
    __syncthreads();

    float oacc[2][4][4] = {};
    float rsum[4] = {0.f, 0.f, 0.f, 0.f};

    for (int tt = 0; tt < NTILES; tt++) {
        CP_WAIT(1);               // K_tt done (V_tt may still be in flight)
        __syncthreads();

        // ---- GEMM1: S = rna(Q)·rna(K)^T — 1-term tf32 (K=64) ----
        float sacc[2][4][4] = {};
        {
            const int mb = wm * 32, nb = wn * 32;
#pragma unroll 2
            for (int j = 0; j < 8; j++) {
                const int k0 = 8 * j + tig;
                uint32_t a[2][4];
#pragma unroll
                for (int i = 0; i < 2; i++) {
                    a[i][0] = __float_as_uint(sm[OQ + k0 * STR + mb + 16 * i + g]);
                    a[i][1] = __float_as_uint(sm[OQ + k0 * STR + mb + 16 * i + g + 8]);
                    a[i][2] = __float_as_uint(sm[OQ + (k0 + 4) * STR + mb + 16 * i + g]);
                    a[i][3] = __float_as_uint(sm[OQ + (k0 + 4) * STR + mb + 16 * i + g + 8]);
                }
#pragma unroll
                for (int f = 0; f < 4; f++) {
                    uint32_t b0r = tf32r(sm[OKS + k0 * STR + nb + 8 * f + g]);
                    uint32_t b1r = tf32r(sm[OKS + (k0 + 4) * STR + nb + 8 * f + g]);
                    mma8(sacc[0][f], a[0], b0r, b1r);
                    mma8(sacc[1][f], a[1], b0r, b1r);
                }
            }
        }
        __syncthreads();          // Ks free -> prefetch K_{tt+1}
        if (tt + 1 < NTILES) {
            const float* kb2 = kb + (size_t)(tt + 1) * NT;
#pragma unroll
            for (int i = 0; i < 4; i++) {
                int idx = t + THREADS * i, c = idx >> 5, q = (idx & 31) * 4;
                cpa16(s2u(sm + OKS + c * STR + q), kb2 + (size_t)c * NMEM + q);
            }
            CP_COMMIT();
        }

        // ---- epilogue: exp -> P (pre-rounded to exact tf32), row sums ----
        {
            const int mb = wm * 32, nb = wn * 32;
            float ps[4] = {0.f, 0.f, 0.f, 0.f};
#pragma unroll
            for (int i = 0; i < 2; i++)
#pragma unroll
                for (int f = 0; f < 4; f++) {
                    float e0 = __uint_as_float(tf32r(__expf(sacc[i][f][0] * 0.125f)));
                    float e1 = __uint_as_float(tf32r(__expf(sacc[i][f][1] * 0.125f)));
                    float e2 = __uint_as_float(tf32r(__expf(sacc[i][f][2] * 0.125f)));
                    float e3 = __uint_as_float(tf32r(__expf(sacc[i][f][3] * 0.125f)));
                    ps[2 * i]     += e0 + e1;
                    ps[2 * i + 1] += e2 + e3;
                    int col = nb + 8 * f + 2 * tig;
                    *(float2*)&sm[OP + (mb + 16 * i + g) * STR + col] =
                        make_float2(e0, e1);
                    *(float2*)&sm[OP + (mb + 16 * i + g + 8) * STR + col] =
                        make_float2(e2, e3);
                }
#pragma unroll
            for (int q = 0; q < 4; q++) {
                ps[q] += __shfl_xor_sync(0xffffffffu, ps[q], 1);
                ps[q] += __shfl_xor_sync(0xffffffffu, ps[q], 2);
                rsum[q] += ps[q];
            }
        }
        if (tt + 1 < NTILES) { CP_WAIT(1); } else { CP_WAIT(0); }   // V_tt done
        __syncthreads();          // Ps visible + V ready

        // ---- GEMM2: O^T += rna(V)·P^T — 1-term tf32 (K=128) ----
        {
            const int cb = wm * 32, mb2 = wn * 32;
#pragma unroll 2
            for (int u = 0; u < 16; u++) {
                const int k0 = 8 * u + tig;
                uint32_t ar[2][4];
#pragma unroll
                for (int i = 0; i < 2; i++) {
                    ar[i][0] = tf32r(sm[OV + (cb + 16 * i + g) * STR + k0]);
                    ar[i][1] = tf32r(sm[OV + (cb + 16 * i + g + 8) * STR + k0]);
                    ar[i][2] = tf32r(sm[OV + (cb + 16 * i + g) * STR + k0 + 4]);
                    ar[i][3] = tf32r(sm[OV + (cb + 16 * i + g + 8) * STR + k0 + 4]);
                }
#pragma unroll
                for (int f = 0; f < 4; f++) {
                    uint32_t b0 = __float_as_uint(sm[OP + (mb2 + 8 * f + g) * STR + k0]);
                    uint32_t b1 = __float_as_uint(sm[OP + (mb2 + 8 * f + g) * STR + k0 + 4]);
                    mma8(oacc[0][f], ar[0], b0, b1);
                    mma8(oacc[1][f], ar[1], b0, b1);
                }
            }
        }
        __syncthreads();          // Vs/Ps free -> prefetch V_{tt+1}
        if (tt + 1 < NTILES) {
            const float* vb2 = vb + (size_t)(tt + 1) * NT;
#pragma unroll
            for (int i = 0; i < 8; i++) {
                int idx = t + THREADS * i, cv = idx >> 5, q = (idx & 31) * 4;
                cpa16(s2u(sm + OV + cv * STR + q), vb2 + (size_t)cv * NMEM + q);
            }
            CP_COMMIT();
        }
    }

    // ---- finalize: row sums -> inv, normalize + store O^T ----
    if (tig == 0) {
        float* rs = sm + ORA + wn * 128;
        const int mb = wm * 32;
        rs[mb + g]      = rsum[0];
        rs[mb + g + 8]  = rsum[1];
        rs[mb + g + 16] = rsum[2];
        rs[mb + g + 24] = rsum[3];
    }
    __syncthreads();
    if (t < 128)
        sm[OINV + t] = 1.0f / (sm[ORA + t] + sm[ORA + 128 + t] +
                               sm[ORA + 256 + t] + sm[ORA + 384 + t]);
    __syncthreads();

    {
        const int cb = wm * 32, mb2 = wn * 32;
#pragma unroll
        for (int i = 0; i < 2; i++)
#pragma unroll
            for (int f = 0; f < 4; f++) {
                int m_ = mb2 + 8 * f + 2 * tig;
                float iv0 = sm[OINV + m_], iv1 = sm[OINV + m_ + 1];
                int cv = cb + 16 * i + g;
                float* o0 = out + ((size_t)b * CVD + cv0 + cv) * MQ + m0 + m_;
                float* o1 = o0 + (size_t)8 * MQ;
                *(float2*)o0 = make_float2(oacc[i][f][0] * iv0, oacc[i][f][1] * iv1);
                *(float2*)o1 = make_float2(oacc[i][f][2] * iv0, oacc[i][f][3] * iv1);
            }
    }
}

// ---------------------------------------------------------------------------
extern "C" void kernel_launch(void* const* d_in, const int* in_sizes, int n_in,
                              void* d_out, int out_size) {
    const float* mk = (const float*)d_in[0];
    const float* qk = (const float*)d_in[1];
    const float* mv = (const float*)d_in[2];
    float* out = (float*)d_out;

    cudaFuncSetAttribute(mr_kernel, cudaFuncAttributeMaxDynamicSharedMemorySize,
                         SMEM_BYTES);
    dim3 grid(MQ / 128, CVD / 128, BATCH);   // 18 x 4 x 4 = 288
    mr_kernel<<<grid, THREADS, SMEM_BYTES>>>(mk, qk, mv, out);
}

// round 11
// speedup vs baseline: 8.0277x; 1.5147x over previous
#include <cuda_runtime.h>
#include <cuda_fp16.h>
#include <cstdint>

#define BATCH 4
#define CKD   64
#define CVD   512
#define NMEM  9216
#define MQ    2304
#define NT    128
#define NTILES (NMEM / NT)   // 72
#define THREADS 512

// half-row strides (in halfs): fragment-load bank-conflict-free
#define SQK 72     // Qh/Kh rows (64 halfs + pad): 36 words -> (4g+tig) banks
#define SPV 136    // Ph/Vh rows (128 halfs + pad): 68 words -> (4g+tig) banks

// smem layout (float offsets)
#define OQH  0                         // Qh  [128 m][72]  f16 ->  4608 f
#define OKH  (OQH + 4608)              // Kh  [128 n][72]  f16 ->  4608 f
#define OPH  (OKH + 4608)              // Ph  [128 m][136] f16 ->  8704 f
#define OVH  (OPH + 8704)              // Vh  [128 cv][136] f16 -> 8704 f
#define OKS  (OVH + 8704)              // Kstg [64 c][132] f32 ->  8448 f
#define OVS  (OKS + 8448)              // Vstg [128 cv][132] f32 -> 16896 f
#define ORA  (OVS + 16896)             // row-sum partials [4][128]
#define OINV (ORA + 512)
#define SM_FLOATS (OINV + 128)
#define SMEM_BYTES (SM_FLOATS * 4)     // 210,432 B

// ---------------------------------------------------------------------------
__device__ __forceinline__ uint32_t s2u(const void* p) {
    uint32_t a;
    asm("{.reg .u64 t; cvta.to.shared.u64 t, %1; cvt.u32.u64 %0, t;}" : "=r"(a) : "l"(p));
    return a;
}
__device__ __forceinline__ void cpa16(uint32_t s, const void* g) {
    asm volatile("cp.async.cg.shared.global [%0], [%1], 16;" :: "r"(s), "l"(g));
}
#define CP_COMMIT() asm volatile("cp.async.commit_group;" ::: "memory")
#define CP_WAIT(N)  asm volatile("cp.async.wait_group %0;" :: "n"(N) : "memory")

// m16n8k16 f16 mma, f32 accumulate.
__device__ __forceinline__ void mma16(float c[4], const uint32_t a[4],
                                      uint32_t b0, uint32_t b1) {
    asm volatile(
        "mma.sync.aligned.m16n8k16.row.col.f32.f16.f16.f32 "
        "{%0,%1,%2,%3}, {%4,%5,%6,%7}, {%8,%9}, {%0,%1,%2,%3};"
        : "+f"(c[0]), "+f"(c[1]), "+f"(c[2]), "+f"(c[3])
        : "r"(a[0]), "r"(a[1]), "r"(a[2]), "r"(a[3]), "r"(b0), "r"(b1));
}
__device__ __forceinline__ uint32_t h2u(__half2 h) {
    return *(uint32_t*)&h;
}

// ---------------------------------------------------------------------------
__global__ __launch_bounds__(THREADS, 1)
void mr_kernel(const float* __restrict__ mk, const float* __restrict__ qk,
               const float* __restrict__ mv, float* __restrict__ out) {
    extern __shared__ float sm[];
    __half* Qh = (__half*)(sm + OQH);
    __half* Kh = (__half*)(sm + OKH);
    __half* Ph = (__half*)(sm + OPH);
    __half* Vh = (__half*)(sm + OVH);

    const int t = threadIdx.x, lane = t & 31;
    const int wid = t >> 5;
    const int g = lane >> 2, tig = lane & 3;
    const int wm = wid & 3, wn = wid >> 2;          // 4 x 4 warp grid
    const int b = blockIdx.z;
    const int m0 = blockIdx.x * 128, cv0 = blockIdx.y * 128;

    const float* qb = qk + (size_t)b * CKD * MQ + m0;
    const float* kb = mk + (size_t)b * CKD * NMEM;
    const float* vb = mv + ((size_t)b * CVD + cv0) * NMEM;

    // ---- prologue: Q -> Kstg, convert to Qh; then commit K0, V0 ----
#pragma unroll
    for (int i = 0; i < 4; i++) {
        int idx = t + THREADS * i, c = idx >> 5, q = (idx & 31) * 4;
        cpa16(s2u(sm + OKS + c * 132 + q), qb + (size_t)c * MQ + q);
    }
    CP_COMMIT(); CP_WAIT(0);
    __syncthreads();
    {   // Kstg[c][m] f32 -> Qh[m][c] f16 packed pairs (transpose)
        const int m = t >> 2, t3 = t & 3;
#pragma unroll
        for (int i = 0; i < 8; i++) {
            int c0 = 2 * t3 + 8 * i;
            float x0 = sm[OKS + c0 * 132 + m];
            float x1 = sm[OKS + (c0 + 1) * 132 + m];
            *(__half2*)&Qh[m * SQK + c0] = __floats2half2_rn(x0, x1);
        }
    }
    __syncthreads();
#pragma unroll
    for (int i = 0; i < 4; i++) {
        int idx = t + THREADS * i, c = idx >> 5, q = (idx & 31) * 4;
        cpa16(s2u(sm + OKS + c * 132 + q), kb + (size_t)c * NMEM + q);
    }
    CP_COMMIT();
#pragma unroll
    for (int i = 0; i < 8; i++) {
        int idx = t + THREADS * i, cv = idx >> 5, q = (idx & 31) * 4;
        cpa16(s2u(sm + OVS + cv * 132 + q), vb + (size_t)cv * NMEM + q);
    }
    CP_COMMIT();

    float oacc[2][4][4] = {};
    float rsum[4] = {0.f, 0.f, 0.f, 0.f};

    for (int tt = 0; tt < NTILES; tt++) {
        CP_WAIT(1);               // K_tt staged (V_tt may still be in flight)
        __syncthreads();

        // ---- convert Kstg[c][n] -> Kh[n][c] f16 packed (transpose) ----
        {
            const int n = t >> 2, t3 = t & 3;
#pragma unroll
            for (int i = 0; i < 8; i++) {
                int c0 = 2 * t3 + 8 * i;
                float x0 = sm[OKS + c0 * 132 + n];
                float x1 = sm[OKS + (c0 + 1) * 132 + n];
                *(__half2*)&Kh[n * SQK + c0] = __floats2half2_rn(x0, x1);
            }
        }
        __syncthreads();
        if (tt + 1 < NTILES) {     // prefetch K_{tt+1} right away
            const float* kb2 = kb + (size_t)(tt + 1) * NT;
#pragma unroll
            for (int i = 0; i < 4; i++) {
                int idx = t + THREADS * i, c = idx >> 5, q = (idx & 31) * 4;
                cpa16(s2u(sm + OKS + c * 132 + q), kb2 + (size_t)c * NMEM + q);
            }
            CP_COMMIT();
        }

        // ---- GEMM1: S = Qh·Kh^T (f16 k16, K=64 -> 4 k-steps) ----
        float sacc[2][4][4] = {};
        {
            const int mb = wm * 32, nb = wn * 32;
#pragma unroll
            for (int j = 0; j < 4; j++) {
                const int col = 16 * j + 2 * tig;
                uint32_t a[2][4];
#pragma unroll
                for (int i = 0; i < 2; i++) {
                    int r = mb + 16 * i + g;
                    a[i][0] = *(uint32_t*)&Qh[r * SQK + col];
                    a[i][1] = *(uint32_t*)&Qh[(r + 8) * SQK + col];
                    a[i][2] = *(uint32_t*)&Qh[r * SQK + col + 8];
                    a[i][3] = *(uint32_t*)&Qh[(r + 8) * SQK + col + 8];
                }
#pragma unroll
                for (int f = 0; f < 4; f++) {
                    int nr = nb + 8 * f + g;
                    uint32_t b0 = *(uint32_t*)&Kh[nr * SQK + col];
                    uint32_t b1 = *(uint32_t*)&Kh[nr * SQK + col + 8];
                    mma16(sacc[0][f], a[0], b0, b1);
                    mma16(sacc[1][f], a[1], b0, b1);
                }
            }
        }

        // ---- epilogue: exp -> Ph (f16 packed pairs), row sums ----
        {
            const int mb = wm * 32, nb = wn * 32;
            float ps[4] = {0.f, 0.f, 0.f, 0.f};
#pragma unroll
            for (int i = 0; i < 2; i++)
#pragma unroll
                for (int f = 0; f < 4; f++) {
                    float e0 = __expf(sacc[i][f][0] * 0.125f);
                    float e1 = __expf(sacc[i][f][1] * 0.125f);
                    float e2 = __expf(sacc[i][f][2] * 0.125f);
                    float e3 = __expf(sacc[i][f][3] * 0.125f);
                    ps[2 * i]     += e0 + e1;
                    ps[2 * i + 1] += e2 + e3;
                    int col = nb + 8 * f + 2 * tig;
                    int r = mb + 16 * i + g;
                    *(__half2*)&Ph[r * SPV + col] = __floats2half2_rn(e0, e1);
                    *(__half2*)&Ph[(r + 8) * SPV + col] = __floats2half2_rn(e2, e3);
                }
#pragma unroll
            for (int q = 0; q < 4; q++) {
                ps[q] += __shfl_xor_sync(0xffffffffu, ps[q], 1);
                ps[q] += __shfl_xor_sync(0xffffffffu, ps[q], 2);
                rsum[q] += ps[q];
            }
        }
        if (tt + 1 < NTILES) { CP_WAIT(1); } else { CP_WAIT(0); }   // V_tt staged
        __syncthreads();           // Ph visible + Vstg ready

        // ---- convert Vstg[cv][n] -> Vh[cv][n] f16 packed (no transpose) ----
        {
            const int cv = t >> 2, jb = t & 3;
#pragma unroll
            for (int i = 0; i < 8; i++) {
                int n4 = (jb + 4 * i) * 4;
                float4 x = *(float4*)&sm[OVS + cv * 132 + n4];
                __half2 h0 = __floats2half2_rn(x.x, x.y);
                __half2 h1 = __floats2half2_rn(x.z, x.w);
                *(uint2*)&Vh[cv * SPV + n4] = make_uint2(h2u(h0), h2u(h1));
            }
        }
        __syncthreads();
        if (tt + 1 < NTILES) {     // prefetch V_{tt+1}
            const float* vb2 = vb + (size_t)(tt + 1) * NT;
#pragma unroll
            for (int i = 0; i < 8; i++) {
                int idx = t + THREADS * i, cv = idx >> 5, q = (idx & 31) * 4;
                cpa16(s2u(sm + OVS + cv * 132 + q), vb2 + (size_t)cv * NMEM + q);
            }
            CP_COMMIT();
        }

        // ---- GEMM2: O^T += Vh·Ph^T (f16 k16, K=128 -> 8 k-steps) ----
        {
            const int cb = wm * 32, mb2 = wn * 32;
#pragma unroll 4
            for (int u = 0; u < 8; u++) {
                const int col = 16 * u + 2 * tig;
                uint32_t a[2][4];
#pragma unroll
                for (int i = 0; i < 2; i++) {
                    int r = cb + 16 * i + g;
                    a[i][0] = *(uint32_t*)&Vh[r * SPV + col];
                    a[i][1] = *(uint32_t*)&Vh[(r + 8) * SPV + col];
                    a[i][2] = *(uint32_t*)&Vh[r * SPV + col + 8];
                    a[i][3] = *(uint32_t*)&Vh[(r + 8) * SPV + col + 8];
                }
#pragma unroll
                for (int f = 0; f < 4; f++) {
                    int mr = mb2 + 8 * f + g;
                    uint32_t b0 = *(uint32_t*)&Ph[mr * SPV + col];
                    uint32_t b1 = *(uint32_t*)&Ph[mr * SPV + col + 8];
                    mma16(oacc[0][f], a[0], b0, b1);
                    mma16(oacc[1][f], a[1], b0, b1);
                }
            }
        }
        __syncthreads();   // Kh/Ph/Vh reads done before next tile's overwrites
    }

    // ---- finalize: row sums -> inv, normalize + store O^T ----
    if (tig == 0) {
        float* rs = sm + ORA + wn * 128;
        const int mb = wm * 32;
        rs[mb + g]      = rsum[0];
        rs[mb + g + 8]  = rsum[1];
        rs[mb + g + 16] = rsum[2];
        rs[mb + g + 24] = rsum[3];
    }
    __syncthreads();
    if (t < 128)
        sm[OINV + t] = 1.0f / (sm[ORA + t] + sm[ORA + 128 + t] +
                               sm[ORA + 256 + t] + sm[ORA + 384 + t]);
    __syncthreads();

    {
        const int cb = wm * 32, mb2 = wn * 32;
#pragma unroll
        for (int i = 0; i < 2; i++)
#pragma unroll
            for (int f = 0; f < 4; f++) {
                int m_ = mb2 + 8 * f + 2 * tig;
                float iv0 = sm[OINV + m_], iv1 = sm[OINV + m_ + 1];
                int cv = cb + 16 * i + g;
                float* o0 = out + ((size_t)b * CVD + cv0 + cv) * MQ + m0 + m_;
                float* o1 = o0 + (size_t)8 * MQ;
                *(float2*)o0 = make_float2(oacc[i][f][0] * iv0, oacc[i][f][1] * iv1);
                *(float2*)o1 = make_float2(oacc[i][f][2] * iv0, oacc[i][f][3] * iv1);
            }
    }
}

// ---------------------------------------------------------------------------
extern "C" void kernel_launch(void* const* d_in, const int* in_sizes, int n_in,
                              void* d_out, int out_size) {
    const float* mk = (const float*)d_in[0];
    const float* qk = (const float*)d_in[1];
    const float* mv = (const float*)d_in[2];
    float* out = (float*)d_out;

    cudaFuncSetAttribute(mr_kernel, cudaFuncAttributeMaxDynamicSharedMemorySize,
                         SMEM_BYTES);
    dim3 grid(MQ / 128, CVD / 128, BATCH);   // 18 x 4 x 4 = 288
    mr_kernel<<<grid, THREADS, SMEM_BYTES>>>(mk, qk, mv, out);
}